// round 9
// baseline (speedup 1.0000x reference)
#include <cuda_runtime.h>
#include <cstddef>

#define B_      128
#define NNZ_    128
#define H_      128
#define KOUT_   4096
#define FDIM_   135909

#define CHUNK_B    32                    // batch rows per pipeline chunk
#define L1B_PER_B  16                    // layer1 blocks per b (warp per h)
#define L2B_PER_B  128                   // layer2 blocks per b (32 outputs each)

// Intermediate val1 [B, H] — device global scratch (no allocations allowed).
__device__ float g_val1[B_ * H_];

// ---------------------------------------------------------------------------
// Mixed pipeline-stage kernel: the grid contains layer1 blocks for one chunk
// of batch rows AND layer2 blocks for an earlier (already-computed) chunk.
// No waiting/spinning — work items are independent by construction; the
// inter-chunk dependency is carried by the kernel-launch ordering.
// Mixing the two traffic classes (random 64B-atom gathers for layer1, random
// coalesced 512B-row reads for layer2) in one resident wave lets DRAM serve
// both patterns concurrently instead of sequentially hitting each pattern's
// sub-roofline ceiling (7.6 TB/s and 5.4 TB/s respectively).
//
//   layer1 block (bid < n_l1_blocks): warp computes one (b,h); lane gathers 4
//     W1 elements (MLP=4), butterfly reduce. 16 blocks per b.
//   layer2 block: warp computes 4 outputs via 4 coalesced float4 row loads,
//     butterfly reduce. 128 blocks per b, val1[b] staged in smem.
// ---------------------------------------------------------------------------
__global__ __launch_bounds__(256) void stage_kernel(
    const float* __restrict__ inv,
    const int*   __restrict__ fidx,
    const float* __restrict__ W1,
    const float* __restrict__ b1,
    const int*   __restrict__ lab,
    const float* __restrict__ W2,
    const float* __restrict__ b2,
    float*       __restrict__ out,
    float*       __restrict__ out_lab,    // may be null
    int l1_b_start, int n_l1_blocks,
    int l2_b_start)
{
    const int tid  = threadIdx.x;
    const int warp = tid >> 5;
    const int lane = tid & 31;

    __shared__ union {
        struct { int idx[NNZ_]; float val[NNZ_]; } l1;
        float4 l2v[32];
    } sm;

    if ((int)blockIdx.x < n_l1_blocks) {
        // ------------------------------ layer 1 ------------------------------
        const int b = l1_b_start + (blockIdx.x >> 4);
        const int h = ((blockIdx.x & 15) << 3) + warp;

        if (tid < 128) sm.l1.idx[tid]       = fidx[(b << 7) + tid];
        else           sm.l1.val[tid - 128] = inv [(b << 7) + tid - 128];
        __syncthreads();

        const float* w = W1 + (size_t)h * FDIM_;
        const int4   i4 = reinterpret_cast<const int4*>(sm.l1.idx)[lane];
        const float4 v4 = reinterpret_cast<const float4*>(sm.l1.val)[lane];

        float acc = __ldg(w + i4.x) * v4.x + __ldg(w + i4.y) * v4.y +
                    __ldg(w + i4.z) * v4.z + __ldg(w + i4.w) * v4.w;

        #pragma unroll
        for (int o = 16; o > 0; o >>= 1)
            acc += __shfl_xor_sync(0xffffffffu, acc, o);

        if (lane == 0)
            g_val1[(b << 7) + h] = fmaxf(acc + __ldg(b1 + h), 0.0f);
        return;
    }

    // -------------------------------- layer 2 --------------------------------
    const int bid2  = (int)blockIdx.x - n_l1_blocks;
    const int b     = l2_b_start + (bid2 >> 7);
    const int kbase = ((bid2 & 127) << 5) + (warp << 2);

    if (tid < 32)
        sm.l2v[tid] = reinterpret_cast<const float4*>(g_val1 + (b << 7))[tid];
    __syncthreads();

    const float4 sv   = sm.l2v[lane];
    const int    base = (b << 12) + kbase;

    int rows[4];
    #pragma unroll
    for (int j = 0; j < 4; j++) rows[j] = lab[base + j];

    float acc[4];
    #pragma unroll
    for (int j = 0; j < 4; j++) {
        const float4 wv = __ldg(reinterpret_cast<const float4*>(W2) +
                                ((size_t)rows[j] << 5) + lane);
        acc[j] = wv.x * sv.x + wv.y * sv.y + wv.z * sv.z + wv.w * sv.w;
    }

    #pragma unroll
    for (int j = 0; j < 4; j++) {
        #pragma unroll
        for (int o = 16; o > 0; o >>= 1)
            acc[j] += __shfl_xor_sync(0xffffffffu, acc[j], o);
    }

    if (lane < 4) {
        const int j = lane;
        const int r = rows[j];
        out[base + j] = acc[j] + __ldg(b2 + r);
        if (out_lab) out_lab[base + j] = (float)r;
    }
}

// ---------------------------------------------------------------------------
extern "C" void kernel_launch(void* const* d_in, const int* in_sizes, int n_in,
                              void* d_out, int out_size)
{
    const float* inv  = (const float*)d_in[0];   // in_values        [B, NNZ]
    const int*   fidx = (const int*)  d_in[1];   // active_in_indices[B, NNZ]
    const int*   lab  = (const int*)  d_in[2];   // active_label_idx [B, KOUT]
    const float* W1   = (const float*)d_in[3];   // [H, FDIM]
    const float* b1   = (const float*)d_in[4];   // [H]
    const float* W2   = (const float*)d_in[5];   // [C, H]
    const float* b2   = (const float*)d_in[6];   // [C]

    float* out = (float*)d_out;
    const int n_val2 = B_ * KOUT_;
    float* out_lab = (out_size >= 2 * n_val2) ? (out + n_val2) : nullptr;

    const int NL1 = CHUNK_B * L1B_PER_B;   // 512 layer1 blocks per chunk
    const int NL2 = CHUNK_B * L2B_PER_B;   // 4096 layer2 blocks per chunk

    // 5-stage software pipeline over 4 chunks of 32 batch rows:
    //   S0: l1(c0)           S1: l1(c1)+l2(c0)   S2: l1(c2)+l2(c1)
    //   S3: l1(c3)+l2(c2)    S4: l2(c3)
    stage_kernel<<<NL1, 256>>>(inv, fidx, W1, b1, lab, W2, b2, out, out_lab,
                               0 * CHUNK_B, NL1, 0);
    stage_kernel<<<NL1 + NL2, 256>>>(inv, fidx, W1, b1, lab, W2, b2, out, out_lab,
                               1 * CHUNK_B, NL1, 0 * CHUNK_B);
    stage_kernel<<<NL1 + NL2, 256>>>(inv, fidx, W1, b1, lab, W2, b2, out, out_lab,
                               2 * CHUNK_B, NL1, 1 * CHUNK_B);
    stage_kernel<<<NL1 + NL2, 256>>>(inv, fidx, W1, b1, lab, W2, b2, out, out_lab,
                               3 * CHUNK_B, NL1, 2 * CHUNK_B);
    stage_kernel<<<NL2, 256>>>(inv, fidx, W1, b1, lab, W2, b2, out, out_lab,
                               0, 0, 3 * CHUNK_B);
}

// round 10
// speedup vs baseline: 1.1868x; 1.1868x over previous
#include <cuda_runtime.h>
#include <cstddef>

#define B_      128
#define NNZ_    128
#define H_      128
#define KOUT_   4096
#define FDIM_   135909

// Intermediate val1 [B, H] — device global scratch (no allocations allowed).
__device__ float g_val1[B_ * H_];

// ---------------------------------------------------------------------------
// Layer 1 (R1-exact: measured optimum, L1tex-wavefront bound ~17.6us):
// val1[b,h] = relu( sum_i v[b,i] * W1[h, fidx[b,i]] + b1[h] )
// One block per b, 128 threads = one per h; indices/values staged in smem;
// i-loop unrolled x16 so ~16 independent gathers are in flight per thread.
// ---------------------------------------------------------------------------
__global__ __launch_bounds__(128) void layer1_kernel(
    const float* __restrict__ inv,
    const int*   __restrict__ fidx,
    const float* __restrict__ W1,
    const float* __restrict__ b1)
{
    const int b = blockIdx.x;
    const int h = threadIdx.x;

    __shared__ int   sidx[NNZ_];
    __shared__ float sval[NNZ_];
    sidx[h] = fidx[(b << 7) + h];
    sval[h] = inv[(b << 7) + h];
    __syncthreads();

    const float* w = W1 + (size_t)h * FDIM_;
    float acc = b1[h];

    #pragma unroll
    for (int i0 = 0; i0 < NNZ_; i0 += 16) {
        float wv[16];
        #pragma unroll
        for (int j = 0; j < 16; j++) wv[j] = __ldg(w + sidx[i0 + j]);
        #pragma unroll
        for (int j = 0; j < 16; j++) acc = fmaf(sval[i0 + j], wv[j], acc);
    }

    g_val1[(b << 7) + h] = fmaxf(acc, 0.0f);
}

// ---------------------------------------------------------------------------
// Layer 2 (R1-exact shape: measured optimum, LTS-cap bound ~41.9us):
//   val2[b,k] = <val1[b,:], W2[lab[b,k],:]> + b2[lab[b,k]]
// Warp = 4 outputs (4 coalesced 512B row loads in flight), block = 8 warps =
// 32 outputs of one b, val1[b] staged in smem. Grid = (B*KOUT)/32 = 16384.
// NEW: single-use streams (lab reads, out/out_lab writes) use evict-first
// cache policy so they don't displace W2 duplicate rows from L2.
// ---------------------------------------------------------------------------
__global__ __launch_bounds__(256) void layer2_kernel(
    const int*   __restrict__ lab,
    const float* __restrict__ W2,
    const float* __restrict__ b2,
    float*       __restrict__ out,
    float*       __restrict__ out_lab)   // may be null
{
    const int warp  = threadIdx.x >> 5;
    const int lane  = threadIdx.x & 31;
    const int b     = blockIdx.x >> 7;                      // 128 blocks per b
    const int kbase = ((blockIdx.x & 127) << 5) + (warp << 2);

    __shared__ float4 s4[32];
    if (threadIdx.x < 32)
        s4[threadIdx.x] = reinterpret_cast<const float4*>(g_val1 + (b << 7))[threadIdx.x];
    __syncthreads();

    const float4 sv = s4[lane];
    const int base = (b << 12) + kbase;

    // labels: read once ever -> evict-first, don't pollute L2
    int rows[4];
    if (lane == 0) {
        const int4 r4 = __ldcs(reinterpret_cast<const int4*>(lab + base));
        rows[0] = r4.x; rows[1] = r4.y; rows[2] = r4.z; rows[3] = r4.w;
    }
    #pragma unroll
    for (int j = 0; j < 4; j++)
        rows[j] = __shfl_sync(0xffffffffu, rows[j], 0);

    float acc[4];
    #pragma unroll
    for (int j = 0; j < 4; j++) {
        const float4 wv = __ldg(reinterpret_cast<const float4*>(W2) +
                                ((size_t)rows[j] << 5) + lane);
        acc[j] = wv.x * sv.x + wv.y * sv.y + wv.z * sv.z + wv.w * sv.w;
    }

    #pragma unroll
    for (int j = 0; j < 4; j++) {
        #pragma unroll
        for (int o = 16; o > 0; o >>= 1)
            acc[j] += __shfl_xor_sync(0xffffffffu, acc[j], o);
    }

    if (lane < 4) {
        const int j = lane;
        const int r = rows[j];
        // outputs: written once, never re-read -> evict-first stores
        __stcs(out + base + j, acc[j] + __ldg(b2 + r));
        if (out_lab) __stcs(out_lab + base + j, (float)r);
    }
}

// ---------------------------------------------------------------------------
extern "C" void kernel_launch(void* const* d_in, const int* in_sizes, int n_in,
                              void* d_out, int out_size)
{
    const float* inv  = (const float*)d_in[0];   // in_values        [B, NNZ]
    const int*   fidx = (const int*)  d_in[1];   // active_in_indices[B, NNZ]
    const int*   lab  = (const int*)  d_in[2];   // active_label_idx [B, KOUT]
    const float* W1   = (const float*)d_in[3];   // [H, FDIM]
    const float* b1   = (const float*)d_in[4];   // [H]
    const float* W2   = (const float*)d_in[5];   // [C, H]
    const float* b2   = (const float*)d_in[6];   // [C]

    float* out = (float*)d_out;
    const int n_val2 = B_ * KOUT_;
    float* out_lab = (out_size >= 2 * n_val2) ? (out + n_val2) : nullptr;

    layer1_kernel<<<B_, 128>>>(inv, fidx, W1, b1);
    layer2_kernel<<<(B_ * KOUT_) / 32, 256>>>(lab, W2, b2, out, out_lab);
}

// round 11
// speedup vs baseline: 1.3180x; 1.1106x over previous
#include <cuda_runtime.h>
#include <cstddef>

#define B_      128
#define NNZ_    128
#define H_      128
#define KOUT_   4096
#define FDIM_   135909

// Intermediate val1 [B, H] — device global scratch (no allocations allowed).
__device__ float g_val1[B_ * H_];

// ---------------------------------------------------------------------------
// Layer 1 (R1-exact: measured optimum, L1tex-wavefront / 64B-atom bound):
// val1[b,h] = relu( sum_i v[b,i] * W1[h, fidx[b,i]] + b1[h] )
// One block per b, 128 threads = one per h; indices/values staged in smem;
// i-loop unrolled x16 so ~16 independent gathers are in flight per thread.
// ---------------------------------------------------------------------------
__global__ __launch_bounds__(128) void layer1_kernel(
    const float* __restrict__ inv,
    const int*   __restrict__ fidx,
    const float* __restrict__ W1,
    const float* __restrict__ b1)
{
    const int b = blockIdx.x;
    const int h = threadIdx.x;

    __shared__ int   sidx[NNZ_];
    __shared__ float sval[NNZ_];
    sidx[h] = fidx[(b << 7) + h];
    sval[h] = inv[(b << 7) + h];
    __syncthreads();

    const float* w = W1 + (size_t)h * FDIM_;
    float acc = b1[h];

    #pragma unroll
    for (int i0 = 0; i0 < NNZ_; i0 += 16) {
        float wv[16];
        #pragma unroll
        for (int j = 0; j < 16; j++) wv[j] = __ldg(w + sidx[i0 + j]);
        #pragma unroll
        for (int j = 0; j < 16; j++) acc = fmaf(sval[i0 + j], wv[j], acc);
    }

    g_val1[(b << 7) + h] = fmaxf(acc, 0.0f);
}

// ---------------------------------------------------------------------------
// Layer 2 (R1-exact shape: measured optimum at ~41.9us / 68% DRAM):
//   val2[b,k] = <val1[b,:], W2[lab[b,k],:]> + b2[lab[b,k]]
// Warp = 4 outputs (4 coalesced 512B row loads in flight), block = 8 warps =
// 32 outputs of one b, val1[b] staged in smem. Grid = (B*KOUT)/32 = 16384.
// Micro-fix vs R1: the b2 gather is issued BEFORE the shfl reduces so its
// ~600-cycle latency overlaps the reduction instead of serializing the tail.
// ---------------------------------------------------------------------------
__global__ __launch_bounds__(256) void layer2_kernel(
    const int*   __restrict__ lab,
    const float* __restrict__ W2,
    const float* __restrict__ b2,
    float*       __restrict__ out,
    float*       __restrict__ out_lab)   // may be null
{
    const int warp  = threadIdx.x >> 5;
    const int lane  = threadIdx.x & 31;
    const int b     = blockIdx.x >> 7;                      // 128 blocks per b
    const int kbase = ((blockIdx.x & 127) << 5) + (warp << 2);

    __shared__ float4 s4[32];
    if (threadIdx.x < 32)
        s4[threadIdx.x] = reinterpret_cast<const float4*>(g_val1 + (b << 7))[threadIdx.x];
    __syncthreads();

    const float4 sv = s4[lane];
    const int base = (b << 12) + kbase;

    int rows[4];
    #pragma unroll
    for (int j = 0; j < 4; j++) rows[j] = lab[base + j];

    float acc[4];
    #pragma unroll
    for (int j = 0; j < 4; j++) {
        const float4 wv = __ldg(reinterpret_cast<const float4*>(W2) +
                                ((size_t)rows[j] << 5) + lane);
        acc[j] = wv.x * sv.x + wv.y * sv.y + wv.z * sv.z + wv.w * sv.w;
    }

    // issue the bias gather before the reduces so it flies during the shfls
    float bias = (lane < 4) ? __ldg(b2 + rows[lane]) : 0.0f;

    #pragma unroll
    for (int j = 0; j < 4; j++) {
        #pragma unroll
        for (int o = 16; o > 0; o >>= 1)
            acc[j] += __shfl_xor_sync(0xffffffffu, acc[j], o);
    }

    if (lane < 4) {
        const int j = lane;
        out[base + j] = acc[j] + bias;
        if (out_lab) out_lab[base + j] = (float)rows[j];
    }
}

// ---------------------------------------------------------------------------
extern "C" void kernel_launch(void* const* d_in, const int* in_sizes, int n_in,
                              void* d_out, int out_size)
{
    const float* inv  = (const float*)d_in[0];   // in_values        [B, NNZ]
    const int*   fidx = (const int*)  d_in[1];   // active_in_indices[B, NNZ]
    const int*   lab  = (const int*)  d_in[2];   // active_label_idx [B, KOUT]
    const float* W1   = (const float*)d_in[3];   // [H, FDIM]
    const float* b1   = (const float*)d_in[4];   // [H]
    const float* W2   = (const float*)d_in[5];   // [C, H]
    const float* b2   = (const float*)d_in[6];   // [C]

    float* out = (float*)d_out;
    const int n_val2 = B_ * KOUT_;
    float* out_lab = (out_size >= 2 * n_val2) ? (out + n_val2) : nullptr;

    layer1_kernel<<<B_, 128>>>(inv, fidx, W1, b1);
    layer2_kernel<<<(B_ * KOUT_) / 32, 256>>>(lab, W2, b2, out, out_lab);
}